// round 11
// baseline (speedup 1.0000x reference)
#include <cuda_runtime.h>
#include <cuda_fp16.h>
#include <cstdint>

namespace {
constexpr int Md = 1024;
constexpr int TX = 32, TY = 16;
constexpr int XP = 40;                   // words per py row (10 float4 slots)
constexpr int CP = 724;                  // f32 staging pitch per cin (2CP%32==8)
constexpr int SGW = 8 * CP;              // staging buffer words (5792)
constexpr int OFF_S = 4608;              // after fp16 weights (9*512 words)
constexpr int SMEM_WORDS = OFF_S + 4 * SGW;   // 27776
constexpr int SMEM_BYTES = SMEM_WORDS * 4;    // 111104 -> 2 CTAs/SM
constexpr int HW = 512 * 512;
constexpr int OP = 36;                   // sOut pitch (conflict-free STS)
}

__device__ float    g_style[8 * 32];
__device__ unsigned g_wmod[8 * 4608];    // [b][tap][cinpair][cout^swz], fp16x2

__device__ __forceinline__ uint32_t s2u(const void* p) {
    uint32_t a;
    asm("{ .reg .u64 t; cvta.to.shared.u64 t, %1; cvt.u32.u64 %0, t; }"
        : "=r"(a) : "l"(p));
    return a;
}
__device__ __forceinline__ void mma_f16(float* d, const unsigned* a,
                                        const unsigned* b) {
    asm volatile(
        "mma.sync.aligned.m16n8k16.row.col.f32.f16.f16.f32 "
        "{%0,%1,%2,%3}, {%4,%5,%6,%7}, {%8,%9}, {%0,%1,%2,%3};\n"
        : "+f"(d[0]), "+f"(d[1]), "+f"(d[2]), "+f"(d[3])
        : "r"(a[0]), "r"(a[1]), "r"(a[2]), "r"(a[3]), "r"(b[0]), "r"(b[1]));
}
__device__ __forceinline__ void cp_wait(int n) {
    switch (n) {
        case 0: asm volatile("cp.async.wait_group 0;" ::: "memory"); break;
        default: asm volatile("cp.async.wait_group 2;" ::: "memory"); break;
    }
}
__device__ __forceinline__ unsigned packh2(float lo, float hi) {
    __half2 h = __floats2half2_rn(lo, hi);
    return *reinterpret_cast<unsigned*>(&h);
}

// one block per (b,c): 128 threads x 8 elems, warp + smem reduce
__global__ void style_kernel(const float* __restrict__ w,
                             const float* __restrict__ sw,
                             const float* __restrict__ sb) {
    __shared__ float red[4];
    const int p = blockIdx.x, b = p >> 5, c = p & 31;
    const int t = threadIdx.x;
    const float4* wv = reinterpret_cast<const float4*>(w + b * Md) + 2 * t;
    const float4* sv = reinterpret_cast<const float4*>(sw + c * Md) + 2 * t;
    float4 a0 = wv[0], s0 = sv[0], a1 = wv[1], s1 = sv[1];
    float acc = a0.x * s0.x + a0.y * s0.y + a0.z * s0.z + a0.w * s0.w +
                a1.x * s1.x + a1.y * s1.y + a1.z * s1.z + a1.w * s1.w;
#pragma unroll
    for (int o = 16; o > 0; o >>= 1)
        acc += __shfl_xor_sync(0xFFFFFFFFu, acc, o);
    if ((t & 31) == 0) red[t >> 5] = acc;
    __syncthreads();
    if (t == 0) g_style[p] = red[0] + red[1] + red[2] + red[3] + sb[c];
}

// g_wmod[b][t9*512 + kp*32 + (co ^ ((kp&3)<<3))] = fp16x2(modulated pair)
__global__ void modw_kernel(const float* __restrict__ kern) {
    int i = blockIdx.x * 256 + threadIdx.x;       // 0 .. 36863
    int b = i / 4608, j = i - b * 4608;
    int t9 = j >> 9, r = j & 511;
    int kp = r >> 5, co = (r & 31) ^ ((kp & 3) << 3);
    float lo = kern[co * 288 + (2 * kp) * 9 + t9]     * g_style[b * 32 + 2 * kp];
    float hi = kern[co * 288 + (2 * kp + 1) * 9 + t9] * g_style[b * 32 + 2 * kp + 1];
    g_wmod[i] = packh2(lo, hi);
}

__global__ __launch_bounds__(256, 2) void conv_hmma3(
    const float* __restrict__ x, float* __restrict__ out) {
    extern __shared__ unsigned sm[];
    float* smf = reinterpret_cast<float*>(sm);

    const int b  = blockIdx.z;
    const int y0 = blockIdx.y * TY;
    const int x0 = blockIdx.x * TX;
    const int tid = threadIdx.x;
    const int w = tid >> 5, lane = tid & 31;
    const int g = lane >> 2, tig = lane & 3;

    // ---- group 0: fp16x2 modulated weights (4608 words = 1152 x 16B) ----
    const uint32_t sm_b = s2u(sm);
    const unsigned* wsrc = g_wmod + b * 4608;
#pragma unroll
    for (int q = 0; q < 5; q++) {
        int idx = q * 256 + tid;
        if (idx < 1152)
            asm volatile("cp.async.cg.shared.global [%0], [%1], 16;"
                         :: "r"(sm_b + (unsigned)(idx * 16)),
                            "l"(wsrc + idx * 4) : "memory");
    }
    asm volatile("cp.async.commit_group;" ::: "memory");

    // ---- groups 1-4: four f32 staging buffers (8 cins each) ----
    const float* xb = x + (size_t)b * 32 * HW;
#pragma unroll
    for (int cg = 0; cg < 4; cg++) {
        const uint32_t base = sm_b + ((unsigned)(OFF_S + cg * SGW) << 2);
#pragma unroll
        for (int bs = 0; bs < 1440; bs += 256) {
            int idx = bs + tid;
            if (idx < 1440) {
                int c  = idx / 180;
                int r  = idx - 180 * c;
                int py = r / 10, j = r - 10 * py;
                int gy = y0 - 1 + py, gxq = x0 - 4 + 4 * j;
                bool ok = ((unsigned)gy < 512u) & (gxq >= 0) & (gxq <= 508);
                const float* gsrc = xb + ((size_t)(cg * 8 + c)) * HW +
                                    (size_t)(ok ? gy : 0) * 512 + (ok ? gxq : 0);
                unsigned zf = ok ? 16u : 0u;
                uint32_t sa = base + ((unsigned)(c * CP + py * XP + 4 * j) << 2);
                asm volatile("cp.async.cg.shared.global [%0], [%1], 16, %2;"
                             :: "r"(sa), "l"(gsrc), "r"(zf) : "memory");
            }
        }
        asm volatile("cp.async.commit_group;" ::: "memory");
    }

    // ---- per-warp tile: 4 y-adjacent m-tiles (rows yb..yb+3), N=32 ----
    const int xh = w & 1;
    const int yb = (w >> 1) * 4;
    int nxo[4];
#pragma unroll
    for (int nt = 0; nt < 4; nt++) nxo[nt] = ((nt ^ tig) << 3) + g;

    float d[4][4][4];
#pragma unroll
    for (int mi = 0; mi < 4; mi++)
#pragma unroll
        for (int nt = 0; nt < 4; nt++)
#pragma unroll
            for (int q = 0; q < 4; q++) d[mi][nt][q] = 0.f;

    // chunk c (c=0,1): cgs 2c, 2c+1 (16 cins); A packed on the fly from f32
    auto compute_chunk = [&](int c) {
        const float* spA = smf + OFF_S + (2 * c) * SGW + 2 * tig * CP;
        const float* spB = spA + SGW;
        const unsigned* bw = sm + (8 * c + tig) * 32;   // + t9*512
#pragma unroll
        for (int kx = 0; kx < 3; kx++) {
            unsigned fa[6][4];
#pragma unroll
            for (int p = 0; p < 6; p++) {
                int ao = (yb + p) * XP + xh * 16 + kx + 3 + g;
                fa[p][0] = packh2(spA[ao],      spA[ao + CP]);
                fa[p][1] = packh2(spA[ao + 8],  spA[ao + CP + 8]);
                fa[p][2] = packh2(spB[ao],      spB[ao + CP]);
                fa[p][3] = packh2(spB[ao + 8],  spB[ao + CP + 8]);
            }
#pragma unroll
            for (int ky = 0; ky < 3; ky++) {
                const unsigned* bt = bw + (ky * 3 + kx) * 512;
                unsigned bf[4][2];
#pragma unroll
                for (int nt = 0; nt < 4; nt++) {
                    bf[nt][0] = bt[nxo[nt]];
                    bf[nt][1] = bt[128 + nxo[nt]];
                }
#pragma unroll
                for (int mi = 0; mi < 4; mi++)
#pragma unroll
                    for (int nt = 0; nt < 4; nt++)
                        mma_f16(d[mi][nt], fa[mi + ky], bf[nt]);
            }
        }
    };

    // ---- pipeline: 2 mainloop barriers ----
    cp_wait(2);            // W + cg0 + cg1 landed
    __syncthreads();
    compute_chunk(0);
    cp_wait(0);            // cg2 + cg3 landed
    __syncthreads();
    compute_chunk(1);

    // ---- epilogue: stage to smem, then coalesced float4 stores ----
    __syncthreads();       // all reads of sW / staging done; reuse as sOut
#pragma unroll
    for (int mi = 0; mi < 4; mi++) {
        int y = yb + mi;
#pragma unroll
        for (int nt = 0; nt < 4; nt++) {
            int co0 = nt * 8 + 2 * tig;
            int base0 = (y * 32 + co0) * OP + xh * 16 + g;
            smf[base0]          = d[mi][nt][0];
            smf[base0 + OP]     = d[mi][nt][1];   // co+1
            smf[base0 + 8]      = d[mi][nt][2];   // x+8
            smf[base0 + OP + 8] = d[mi][nt][3];
        }
    }
    __syncthreads();
#pragma unroll
    for (int it = 0; it < 16; it++) {
        int R = it * 32 + w * 4 + (lane >> 3);    // R = y*32 + co
        int y = R >> 5, co = R & 31;
        float4 v = *reinterpret_cast<const float4*>(smf + R * OP + 4 * (lane & 7));
        *reinterpret_cast<float4*>(out + ((size_t)(b * 32 + co)) * HW +
                                   (size_t)(y0 + y) * 512 + x0 + 4 * (lane & 7)) = v;
    }
}

extern "C" void kernel_launch(void* const* d_in, const int* in_sizes, int n_in,
                              void* d_out, int out_size) {
    const float* x    = (const float*)d_in[0];
    const float* wmap = (const float*)d_in[1];
    const float* kern = (const float*)d_in[2];
    const float* sw   = (const float*)d_in[3];
    const float* sbv  = (const float*)d_in[4];
    float* out = (float*)d_out;

    cudaFuncSetAttribute(conv_hmma3,
                         cudaFuncAttributeMaxDynamicSharedMemorySize, SMEM_BYTES);
    style_kernel<<<256, 128>>>(wmap, sw, sbv);
    modw_kernel<<<144, 256>>>(kern);
    dim3 grid(512 / TX, 512 / TY, 8);
    conv_hmma3<<<grid, 256, SMEM_BYTES>>>(x, out);
}

// round 13
// speedup vs baseline: 1.0674x; 1.0674x over previous
#include <cuda_runtime.h>
#include <cuda_fp16.h>
#include <cstdint>

namespace {
constexpr int Md = 1024;
constexpr int TX = 32, TY = 16;
constexpr int XP   = 40;                 // words per py row (10 float4 slots)
constexpr int CP32 = 720;                // f32 staging pitch per cin (18*40)
constexpr int SG   = 8 * CP32;           // staging buffer words (5760)
constexpr int HP   = 728;                // fp16 tile pitch per cin-pair (%32==24)
constexpr int OFF_S0 = 4608;             // after fp16 weights (9*512 words)
constexpr int OFF_S1 = OFF_S0 + SG;
constexpr int OFF_H  = OFF_S1 + SG;      // 16128
constexpr int SMEM_WORDS = OFF_H + 16 * HP;   // 27776
constexpr int SMEM_BYTES = SMEM_WORDS * 4;    // 111104 -> 2 CTAs/SM
constexpr int HW = 512 * 512;
constexpr int OP = 36;                   // sOut pitch (conflict-free STS)
}

__device__ float    g_style[8 * 32];
__device__ unsigned g_wmod[8 * 4608];    // [b][tap][cinpair][cout^swz], fp16x2

__device__ __forceinline__ uint32_t s2u(const void* p) {
    uint32_t a;
    asm("{ .reg .u64 t; cvta.to.shared.u64 t, %1; cvt.u32.u64 %0, t; }"
        : "=r"(a) : "l"(p));
    return a;
}
__device__ __forceinline__ void mma_f16(float* d, const unsigned* a,
                                        const unsigned* b) {
    asm volatile(
        "mma.sync.aligned.m16n8k16.row.col.f32.f16.f16.f32 "
        "{%0,%1,%2,%3}, {%4,%5,%6,%7}, {%8,%9}, {%0,%1,%2,%3};\n"
        : "+f"(d[0]), "+f"(d[1]), "+f"(d[2]), "+f"(d[3])
        : "r"(a[0]), "r"(a[1]), "r"(a[2]), "r"(a[3]), "r"(b[0]), "r"(b[1]));
}
__device__ __forceinline__ void cp_wait(int n) {
    switch (n) {
        case 0: asm volatile("cp.async.wait_group 0;" ::: "memory"); break;
        case 1: asm volatile("cp.async.wait_group 1;" ::: "memory"); break;
        default: asm volatile("cp.async.wait_group 2;" ::: "memory"); break;
    }
}
__device__ __forceinline__ unsigned packh2(float lo, float hi) {
    __half2 h = __floats2half2_rn(lo, hi);
    return *reinterpret_cast<unsigned*>(&h);
}

// one block per (b,c): 128 threads x 8 elems, warp + smem reduce
__global__ void style_kernel(const float* __restrict__ w,
                             const float* __restrict__ sw,
                             const float* __restrict__ sb) {
    __shared__ float red[4];
    const int p = blockIdx.x, b = p >> 5, c = p & 31;
    const int t = threadIdx.x;
    const float4* wv = reinterpret_cast<const float4*>(w + b * Md) + 2 * t;
    const float4* sv = reinterpret_cast<const float4*>(sw + c * Md) + 2 * t;
    float4 a0 = wv[0], s0 = sv[0], a1 = wv[1], s1 = sv[1];
    float acc = a0.x * s0.x + a0.y * s0.y + a0.z * s0.z + a0.w * s0.w +
                a1.x * s1.x + a1.y * s1.y + a1.z * s1.z + a1.w * s1.w;
#pragma unroll
    for (int o = 16; o > 0; o >>= 1)
        acc += __shfl_xor_sync(0xFFFFFFFFu, acc, o);
    if ((t & 31) == 0) red[t >> 5] = acc;
    __syncthreads();
    if (t == 0) g_style[p] = red[0] + red[1] + red[2] + red[3] + sb[c];
}

// g_wmod[b][t9*512 + kp*32 + (co ^ ((kp&3)<<3))] = fp16x2(modulated pair)
__global__ void modw_kernel(const float* __restrict__ kern) {
    int i = blockIdx.x * 256 + threadIdx.x;       // 0 .. 36863
    int b = i / 4608, j = i - b * 4608;
    int t9 = j >> 9, r = j & 511;
    int kp = r >> 5, co = (r & 31) ^ ((kp & 3) << 3);
    float lo = kern[co * 288 + (2 * kp) * 9 + t9]     * g_style[b * 32 + 2 * kp];
    float hi = kern[co * 288 + (2 * kp + 1) * 9 + t9] * g_style[b * 32 + 2 * kp + 1];
    g_wmod[i] = packh2(lo, hi);
}

__global__ __launch_bounds__(256, 2) void conv_hmma4(
    const float* __restrict__ x, float* __restrict__ out) {
    extern __shared__ unsigned sm[];
    float* smf = reinterpret_cast<float*>(sm);

    const int b  = blockIdx.z;
    const int y0 = blockIdx.y * TY;
    const int x0 = blockIdx.x * TX;
    const int tid = threadIdx.x;
    const int w = tid >> 5, lane = tid & 31;
    const int g = lane >> 2, tig = lane & 3;

    // ---- group 0: fp16x2 modulated weights (4608 words = 1152 x 16B) ----
    const uint32_t sm_b = s2u(sm);
    const unsigned* wsrc = g_wmod + b * 4608;
#pragma unroll
    for (int q = 0; q < 5; q++) {
        int idx = q * 256 + tid;
        if (idx < 1152)
            asm volatile("cp.async.cg.shared.global [%0], [%1], 16;"
                         :: "r"(sm_b + (unsigned)(idx * 16)),
                            "l"(wsrc + idx * 4) : "memory");
    }
    asm volatile("cp.async.commit_group;" ::: "memory");

    const float* xb = x + (size_t)b * 32 * HW;

    // Self-owned staging: unit u=(pp,py,j) is loaded AND converted by the same
    // thread, so load->convert and buffer reuse need no __syncthreads.
    auto issue_cg = [&](int cg) {
        const uint32_t base = sm_b + ((unsigned)(cg & 1 ? OFF_S1 : OFF_S0) << 2);
#pragma unroll
        for (int bs = 0; bs < 720; bs += 256) {
            int u = bs + tid;
            if (u < 720) {
                int pp = u / 180, r = u - 180 * pp;
                int py = r / 10, j = r - 10 * py;
                int gy = y0 - 1 + py, gxq = x0 - 4 + 4 * j;
                bool ok = ((unsigned)gy < 512u) & (gxq >= 0) & (gxq <= 508);
                unsigned zf = ok ? 16u : 0u;
                int o = py * XP + 4 * j;
#pragma unroll
                for (int c2 = 0; c2 < 2; c2++) {
                    const float* gsrc = xb +
                        ((size_t)(cg * 8 + 2 * pp + c2)) * HW +
                        (size_t)(ok ? gy : 0) * 512 + (ok ? gxq : 0);
                    uint32_t sa = base + ((unsigned)((2 * pp + c2) * CP32 + o) << 2);
                    asm volatile("cp.async.cg.shared.global [%0], [%1], 16, %2;"
                                 :: "r"(sa), "l"(gsrc), "r"(zf) : "memory");
                }
            }
        }
        asm volatile("cp.async.commit_group;" ::: "memory");
    };

    auto convert_cg = [&](int cg) {
        const float* sp = smf + (cg & 1 ? OFF_S1 : OFF_S0);
        unsigned*    hp = sm + OFF_H + (cg * 4) * HP;
#pragma unroll
        for (int bs = 0; bs < 720; bs += 256) {
            int u = bs + tid;
            if (u < 720) {
                int pp = u / 180, r = u - 180 * pp;
                int py = r / 10, j = r - 10 * py;
                int o = py * XP + 4 * j;
                float4 va = *reinterpret_cast<const float4*>(sp + 2 * pp * CP32 + o);
                float4 vb = *reinterpret_cast<const float4*>(sp + (2 * pp + 1) * CP32 + o);
                uint4 ov;
                ov.x = packh2(va.x, vb.x);
                ov.y = packh2(va.y, vb.y);
                ov.z = packh2(va.z, vb.z);
                ov.w = packh2(va.w, vb.w);
                *reinterpret_cast<uint4*>(hp + pp * HP + o) = ov;
            }
        }
    };

    issue_cg(0);
    issue_cg(1);

    // ---- per-warp tile: 4 y-adjacent m-tiles (rows yb..yb+3), N=32 ----
    const int xh = w & 1;
    const int yb = (w >> 1) * 4;
    int nxo[4];
#pragma unroll
    for (int nt = 0; nt < 4; nt++) nxo[nt] = ((nt ^ tig) << 3) + g;

    float d[4][4][4];
#pragma unroll
    for (int mi = 0; mi < 4; mi++)
#pragma unroll
        for (int nt = 0; nt < 4; nt++)
#pragma unroll
            for (int q = 0; q < 4; q++) d[mi][nt][q] = 0.f;

    // one kx slice of chunk c (c=0,1): cins 16c..16c+15 = pairs 8c..8c+7
    auto compute_kx = [&](int c, int kx) {
        const unsigned* hb = sm + OFF_H + (8 * c + tig) * HP;
        const unsigned* bw = sm + (8 * c + tig) * 32;   // + t9*512
        unsigned fa[6][4];
#pragma unroll
        for (int p = 0; p < 6; p++) {
            int ao = (yb + p) * XP + xh * 16 + kx + 3 + g;
            fa[p][0] = hb[ao];
            fa[p][1] = hb[ao + 8];
            fa[p][2] = hb[ao + 4 * HP];
            fa[p][3] = hb[ao + 4 * HP + 8];
        }
#pragma unroll
        for (int ky = 0; ky < 3; ky++) {
            const unsigned* bt = bw + (ky * 3 + kx) * 512;
            unsigned bf[4][2];
#pragma unroll
            for (int nt = 0; nt < 4; nt++) {
                bf[nt][0] = bt[nxo[nt]];
                bf[nt][1] = bt[128 + nxo[nt]];
            }
#pragma unroll
            for (int mi = 0; mi < 4; mi++)
#pragma unroll
                for (int nt = 0; nt < 4; nt++)
                    mma_f16(d[mi][nt], fa[mi + ky], bf[nt]);
        }
    };

    // ---- pipeline: converts 2/3 interleaved into chunk0 compute ----
    cp_wait(1);            // W + cg0 landed (self-visible)
    convert_cg(0);
    issue_cg(2);           // reuse s0 (self-owned, already consumed)
    cp_wait(1);            // cg1 landed
    convert_cg(1);
    issue_cg(3);           // reuse s1
    __syncthreads();       // hp pairs 0-7 + weights visible CTA-wide

    compute_kx(0, 0);
    cp_wait(1);            // cg2 landed (overlapped with kx0 compute)
    convert_cg(2);         // hp pairs 8-11 (disjoint from chunk0 reads)
    compute_kx(0, 1);
    cp_wait(0);            // cg3 landed
    convert_cg(3);         // hp pairs 12-15
    compute_kx(0, 2);

    __syncthreads();       // hp pairs 8-15 visible
    compute_kx(1, 0);
    compute_kx(1, 1);
    compute_kx(1, 2);

    // ---- epilogue: stage to smem, then coalesced float4 stores ----
    __syncthreads();       // all reads of sW / tiles done; reuse as sOut
#pragma unroll
    for (int mi = 0; mi < 4; mi++) {
        int y = yb + mi;
#pragma unroll
        for (int nt = 0; nt < 4; nt++) {
            int co0 = nt * 8 + 2 * tig;
            int base0 = (y * 32 + co0) * OP + xh * 16 + g;
            smf[base0]          = d[mi][nt][0];
            smf[base0 + OP]     = d[mi][nt][1];   // co+1
            smf[base0 + 8]      = d[mi][nt][2];   // x+8
            smf[base0 + OP + 8] = d[mi][nt][3];
        }
    }
    __syncthreads();
#pragma unroll
    for (int it = 0; it < 16; it++) {
        int R = it * 32 + w * 4 + (lane >> 3);    // R = y*32 + co
        int y = R >> 5, co = R & 31;
        float4 v = *reinterpret_cast<const float4*>(smf + R * OP + 4 * (lane & 7));
        *reinterpret_cast<float4*>(out + ((size_t)(b * 32 + co)) * HW +
                                   (size_t)(y0 + y) * 512 + x0 + 4 * (lane & 7)) = v;
    }
}

extern "C" void kernel_launch(void* const* d_in, const int* in_sizes, int n_in,
                              void* d_out, int out_size) {
    const float* x    = (const float*)d_in[0];
    const float* wmap = (const float*)d_in[1];
    const float* kern = (const float*)d_in[2];
    const float* sw   = (const float*)d_in[3];
    const float* sbv  = (const float*)d_in[4];
    float* out = (float*)d_out;

    cudaFuncSetAttribute(conv_hmma4,
                         cudaFuncAttributeMaxDynamicSharedMemorySize, SMEM_BYTES);
    style_kernel<<<256, 128>>>(wmap, sw, sbv);
    modw_kernel<<<144, 256>>>(kern);
    dim3 grid(512 / TX, 512 / TY, 8);
    conv_hmma4<<<grid, 256, SMEM_BYTES>>>(x, out);
}